// round 5
// baseline (speedup 1.0000x reference)
#include <cuda_runtime.h>
#include <cuda_bf16.h>

// ---------------------------------------------------------------------------
// EdgeClassifierGNN: 2x SAGEConv(mean) + edge MLP, refactored:
//   h1 = relu( (scatter_mean(x)) @ W1l + x @ W1r + b1l )
//   h2 = relu( (scatter_mean(h1)) @ W2l + h1 @ W2r + b2l )
//   A  = h2 @ Wm1[0:256,:]      B = h2 @ Wm1[256:512,:]
//   out[e] = relu(A[src]+B[dst]+bm1) @ Wm2 + bm2
// edge_index arrives as int32 [2, E] (harness converts int64 -> int32).
// ---------------------------------------------------------------------------

#define MAXN 50000
#define MAXE 800000
#define D 256

__device__ __align__(16) float g_msg [(size_t)MAXN * D];
__device__ __align__(16) float g_deg [MAXN];
__device__ __align__(16) float g_rdeg[MAXN];
__device__ __align__(16) float g_h1  [(size_t)MAXN * D];
__device__ __align__(16) float g_h2  [(size_t)MAXN * D];
__device__ __align__(16) float g_Ab  [(size_t)MAXN * D];
__device__ __align__(16) float g_Bb  [(size_t)MAXN * D];

// ---------------------------------------------------------------- zero
__global__ void zero_kernel(float4* __restrict__ p, int n4) {
    for (int i = blockIdx.x * blockDim.x + threadIdx.x; i < n4;
         i += gridDim.x * blockDim.x)
        p[i] = make_float4(0.f, 0.f, 0.f, 0.f);
}

// ---------------------------------------------------------------- scatter
// one warp per edge: msg[dst] += X[src]; optionally deg[dst] += 1
__global__ void __launch_bounds__(256) scatter_kernel(
    const int* __restrict__ ei, const float* __restrict__ X,
    float* __restrict__ msg, float* __restrict__ deg, int E)
{
    int e = blockIdx.x * 8 + (threadIdx.x >> 5);
    if (e >= E) return;
    int lane = threadIdx.x & 31;
    int src = ei[e];
    int dst = ei[E + e];

    const float4* xs = (const float4*)(X + (size_t)src * D);
    float* mp = msg + (size_t)dst * D;
#pragma unroll
    for (int i = 0; i < 2; i++) {
        int q = lane + i * 32;                 // float4 index 0..63
        float4 v = xs[q];
        float* p = mp + q * 4;
        atomicAdd(p + 0, v.x);
        atomicAdd(p + 1, v.y);
        atomicAdd(p + 2, v.z);
        atomicAdd(p + 3, v.w);
    }
    if (deg != nullptr && lane == 0) atomicAdd(deg + dst, 1.0f);
}

// ---------------------------------------------------------------- rdeg
__global__ void rdeg_kernel(const float* __restrict__ deg,
                            float* __restrict__ rdeg, int n)
{
    int i = blockIdx.x * blockDim.x + threadIdx.x;
    if (i < n) rdeg[i] = 1.0f / fmaxf(deg[i], 1.0f);
}

// ---------------------------------------------------------------- GEMM
// C[M,256] = act( scale(A1)@B1 + A2@B2 + bias ),  K = 256 per source
//   A1 optionally row-scaled by rdeg.  A2 may be nullptr (single source).
//   B matrices are [256, 256] row-major (K-major rows, N contiguous).
#define BM 128
#define BN 64
#define BK 16

__global__ void __launch_bounds__(256) gemm_kernel(
    const float* __restrict__ A1, const float* __restrict__ B1,
    const float* __restrict__ A2, const float* __restrict__ B2,
    const float* __restrict__ rdeg, const float* __restrict__ bias,
    float* __restrict__ C, int M, int relu)
{
    __shared__ float As[BK][BM];
    __shared__ float Bs[BK][BN];

    int tid  = threadIdx.x;
    int m0   = blockIdx.y * BM;
    int n0   = blockIdx.x * BN;
    int trow = tid >> 4;    // 0..15 -> rows trow*8 .. +7
    int tcol = tid & 15;    // 0..15 -> cols tcol*4 .. +3

    float acc[8][4];
#pragma unroll
    for (int i = 0; i < 8; i++)
#pragma unroll
        for (int j = 0; j < 4; j++) acc[i][j] = 0.f;

    int nphase = (A2 != nullptr) ? 2 : 1;
    for (int ph = 0; ph < nphase; ph++) {
        const float* Ag = ph ? A2 : A1;
        const float* Bg = ph ? B2 : B1;
        bool doScale = (ph == 0) && (rdeg != nullptr);

        for (int k0 = 0; k0 < D; k0 += BK) {
            // load A tile (128 rows x 16 k), transpose into As[k][m]
#pragma unroll
            for (int u = 0; u < 2; u++) {
                int v   = tid + u * 256;       // float4 id 0..511
                int row = v >> 2;
                int kq  = (v & 3) * 4;
                float4 val = make_float4(0.f, 0.f, 0.f, 0.f);
                int gm = m0 + row;
                if (gm < M) {
                    val = *(const float4*)(Ag + (size_t)gm * D + k0 + kq);
                    if (doScale) {
                        float s = rdeg[gm];
                        val.x *= s; val.y *= s; val.z *= s; val.w *= s;
                    }
                }
                As[kq + 0][row] = val.x;
                As[kq + 1][row] = val.y;
                As[kq + 2][row] = val.z;
                As[kq + 3][row] = val.w;
            }
            // load B tile (16 k x 64 n)
            {
                int row = tid >> 4;
                int nq  = (tid & 15) * 4;
                float4 val = *(const float4*)(Bg + (size_t)(k0 + row) * D + n0 + nq);
                *(float4*)&Bs[row][nq] = val;
            }
            __syncthreads();

#pragma unroll
            for (int k = 0; k < BK; k++) {
                float a[8], b[4];
                *(float4*)&a[0] = *(const float4*)&As[k][trow * 8];
                *(float4*)&a[4] = *(const float4*)&As[k][trow * 8 + 4];
                *(float4*)&b[0] = *(const float4*)&Bs[k][tcol * 4];
#pragma unroll
                for (int i = 0; i < 8; i++)
#pragma unroll
                    for (int j = 0; j < 4; j++)
                        acc[i][j] = fmaf(a[i], b[j], acc[i][j]);
            }
            __syncthreads();
        }
    }

    float4 bv = make_float4(0.f, 0.f, 0.f, 0.f);
    if (bias != nullptr) bv = *(const float4*)(bias + n0 + tcol * 4);

#pragma unroll
    for (int i = 0; i < 8; i++) {
        int gm = m0 + trow * 8 + i;
        if (gm < M) {
            float4 o;
            o.x = acc[i][0] + bv.x;
            o.y = acc[i][1] + bv.y;
            o.z = acc[i][2] + bv.z;
            o.w = acc[i][3] + bv.w;
            if (relu) {
                o.x = fmaxf(o.x, 0.f); o.y = fmaxf(o.y, 0.f);
                o.z = fmaxf(o.z, 0.f); o.w = fmaxf(o.w, 0.f);
            }
            *(float4*)(C + (size_t)gm * D + n0 + tcol * 4) = o;
        }
    }
}

// ---------------------------------------------------------------- edge MLP
// out[e,:2] = relu(A[src]+B[dst]+bm1) @ Wm2 + bm2  ; one warp per edge
__global__ void __launch_bounds__(256) edge_kernel(
    const int* __restrict__ ei,
    const float* __restrict__ Ab, const float* __restrict__ Bb,
    const float* __restrict__ bm1, const float* __restrict__ Wm2,
    const float* __restrict__ bm2, float* __restrict__ out, int E)
{
    int e = blockIdx.x * 8 + (threadIdx.x >> 5);
    if (e >= E) return;
    int lane = threadIdx.x & 31;
    int src = ei[e];
    int dst = ei[E + e];

    const float4* a  = (const float4*)(Ab + (size_t)src * D);
    const float4* b  = (const float4*)(Bb + (size_t)dst * D);
    const float4* bi = (const float4*)bm1;

    float acc0 = 0.f, acc1 = 0.f;
#pragma unroll
    for (int i = 0; i < 2; i++) {
        int q = lane + i * 32;          // float4 id, covers j = q*4..q*4+3
        float4 av = a[q];
        float4 bv = b[q];
        float4 cv = bi[q];
        float h0 = fmaxf(av.x + bv.x + cv.x, 0.f);
        float h1 = fmaxf(av.y + bv.y + cv.y, 0.f);
        float h2 = fmaxf(av.z + bv.z + cv.z, 0.f);
        float h3 = fmaxf(av.w + bv.w + cv.w, 0.f);
        // Wm2 rows j (256x2 row-major): 8 floats for 4 rows
        const float4* w = (const float4*)(Wm2 + q * 8);
        float4 w0 = w[0];   // {W[j0][0], W[j0][1], W[j1][0], W[j1][1]}
        float4 w1 = w[1];
        acc0 = fmaf(h0, w0.x, acc0); acc1 = fmaf(h0, w0.y, acc1);
        acc0 = fmaf(h1, w0.z, acc0); acc1 = fmaf(h1, w0.w, acc1);
        acc0 = fmaf(h2, w1.x, acc0); acc1 = fmaf(h2, w1.y, acc1);
        acc0 = fmaf(h3, w1.z, acc0); acc1 = fmaf(h3, w1.w, acc1);
    }
#pragma unroll
    for (int off = 16; off > 0; off >>= 1) {
        acc0 += __shfl_xor_sync(0xFFFFFFFFu, acc0, off);
        acc1 += __shfl_xor_sync(0xFFFFFFFFu, acc1, off);
    }
    if (lane == 0) {
        out[(size_t)e * 2 + 0] = acc0 + bm2[0];
        out[(size_t)e * 2 + 1] = acc1 + bm2[1];
    }
}

// ---------------------------------------------------------------- launch
extern "C" void kernel_launch(void* const* d_in, const int* in_sizes, int n_in,
                              void* d_out, int out_size)
{
    const float* x   = (const float*)d_in[0];
    const int*   ei  = (const int*)d_in[1];        // int32 [2, E]
    const float* W1l = (const float*)d_in[2];
    const float* b1l = (const float*)d_in[3];
    const float* W1r = (const float*)d_in[4];
    const float* W2l = (const float*)d_in[5];
    const float* b2l = (const float*)d_in[6];
    const float* W2r = (const float*)d_in[7];
    const float* Wm1 = (const float*)d_in[8];      // [512, 256]
    const float* bm1 = (const float*)d_in[9];
    const float* Wm2 = (const float*)d_in[10];     // [256, 2]
    const float* bm2 = (const float*)d_in[11];
    float*       out = (float*)d_out;

    int M = in_sizes[0] / D;       // 50000
    int E = in_sizes[1] / 2;       // 800000

    float *msg, *deg, *rdeg, *h1, *h2, *Ab, *Bb;
    cudaGetSymbolAddress((void**)&msg,  g_msg);
    cudaGetSymbolAddress((void**)&deg,  g_deg);
    cudaGetSymbolAddress((void**)&rdeg, g_rdeg);
    cudaGetSymbolAddress((void**)&h1,   g_h1);
    cudaGetSymbolAddress((void**)&h2,   g_h2);
    cudaGetSymbolAddress((void**)&Ab,   g_Ab);
    cudaGetSymbolAddress((void**)&Bb,   g_Bb);

    int msg4 = M * D / 4;
    dim3 ggrid(D / BN, (M + BM - 1) / BM);
    int eblocks = (E + 7) / 8;

    // ---- layer 1 ----
    zero_kernel<<<2048, 256>>>((float4*)msg, msg4);
    zero_kernel<<<64, 256>>>((float4*)deg, M / 4);
    scatter_kernel<<<eblocks, 256>>>(ei, x, msg, deg, E);
    rdeg_kernel<<<(M + 255) / 256, 256>>>(deg, rdeg, M);
    gemm_kernel<<<ggrid, 256>>>(msg, W1l, x, W1r, rdeg, b1l, h1, M, 1);

    // ---- layer 2 ----
    zero_kernel<<<2048, 256>>>((float4*)msg, msg4);
    scatter_kernel<<<eblocks, 256>>>(ei, h1, msg, nullptr, E);
    gemm_kernel<<<ggrid, 256>>>(msg, W2l, h1, W2r, rdeg, b2l, h2, M, 1);

    // ---- edge MLP node precompute: A = h2 @ Wm1_top, B = h2 @ Wm1_bot ----
    gemm_kernel<<<ggrid, 256>>>(h2, Wm1,            nullptr, nullptr,
                                nullptr, nullptr, Ab, M, 0);
    gemm_kernel<<<ggrid, 256>>>(h2, Wm1 + 256 * D,  nullptr, nullptr,
                                nullptr, nullptr, Bb, M, 0);

    // ---- per-edge ----
    edge_kernel<<<eblocks, 256>>>(ei, Ab, Bb, bm1, Wm2, bm2, out, E);
}

// round 6
// speedup vs baseline: 1.3212x; 1.3212x over previous
#include <cuda_runtime.h>
#include <cuda_bf16.h>

// ---------------------------------------------------------------------------
// EdgeClassifierGNN: 2x SAGEConv(mean) + edge MLP.
//   h1 = relu( (scatter_mean(x)) @ W1l + x @ W1r + b1l )
//   h2 = relu( (scatter_mean(h1)) @ W2l + h1 @ W2r + b2l )
//   A  = h2 @ Wm1[0:256,:]   B = h2 @ Wm1[256:512,:]
//   out[e] = relu(A[src]+B[dst]+bm1) @ Wm2 + bm2
// GEMMs on tensor cores via mma.sync m16n8k8 tf32 (fp32 accum).
// ---------------------------------------------------------------------------

#define MAXN 50000
#define MAXE 800000
#define D 256

__device__ __align__(16) float g_msg [(size_t)MAXN * D];
__device__ __align__(16) float g_deg [MAXN];
__device__ __align__(16) float g_rdeg[MAXN];
__device__ __align__(16) float g_h1  [(size_t)MAXN * D];
__device__ __align__(16) float g_h2  [(size_t)MAXN * D];
__device__ __align__(16) float g_Ab  [(size_t)MAXN * D];
__device__ __align__(16) float g_Bb  [(size_t)MAXN * D];

// ---------------------------------------------------------------- zero
__global__ void zero_kernel(float4* __restrict__ p, int n4) {
    for (int i = blockIdx.x * blockDim.x + threadIdx.x; i < n4;
         i += gridDim.x * blockDim.x)
        p[i] = make_float4(0.f, 0.f, 0.f, 0.f);
}

// ---------------------------------------------------------------- scatter
__global__ void __launch_bounds__(256) scatter_kernel(
    const int* __restrict__ ei, const float* __restrict__ X,
    float* __restrict__ msg, float* __restrict__ deg, int E)
{
    int e = blockIdx.x * 8 + (threadIdx.x >> 5);
    if (e >= E) return;
    int lane = threadIdx.x & 31;
    int src = ei[e];
    int dst = ei[E + e];

    const float4* xs = (const float4*)(X + (size_t)src * D);
    float* mp = msg + (size_t)dst * D;
#pragma unroll
    for (int i = 0; i < 2; i++) {
        int q = lane + i * 32;
        float4 v = xs[q];
        float* p = mp + q * 4;
        atomicAdd(p + 0, v.x);
        atomicAdd(p + 1, v.y);
        atomicAdd(p + 2, v.z);
        atomicAdd(p + 3, v.w);
    }
    if (deg != nullptr && lane == 0) atomicAdd(deg + dst, 1.0f);
}

// ---------------------------------------------------------------- rdeg
__global__ void rdeg_kernel(const float* __restrict__ deg,
                            float* __restrict__ rdeg, int n)
{
    int i = blockIdx.x * blockDim.x + threadIdx.x;
    if (i < n) rdeg[i] = 1.0f / fmaxf(deg[i], 1.0f);
}

// ---------------------------------------------------------------- tf32 GEMM
// C[M,256] = act( scale(A1)@B1 + A2@B2 + bias ), K = 256 per source.
// Block tile 128x128, BK=16, 8 warps (2 m x 4 n), warp tile 64x32.
#define GBM 128
#define GBN 128
#define GBK 16
#define AS_STRIDE 20    // 16 + 4 pad  (conflict-free fragment reads)
#define BS_STRIDE 136   // 128 + 8 pad

__device__ __forceinline__ unsigned f2tf32(float f) {
    unsigned u;
    asm("cvt.rna.tf32.f32 %0, %1;" : "=r"(u) : "f"(f));
    return u;
}

__global__ void __launch_bounds__(256) mma_gemm_kernel(
    const float* __restrict__ A1, const float* __restrict__ B1,
    const float* __restrict__ A2, const float* __restrict__ B2,
    const float* __restrict__ rdeg, const float* __restrict__ bias,
    float* __restrict__ C, int M, int relu)
{
    __shared__ float As[GBM * AS_STRIDE];
    __shared__ float Bs[GBK * BS_STRIDE];

    int tid    = threadIdx.x;
    int warp   = tid >> 5;
    int lane   = tid & 31;
    int warp_m = warp >> 2;            // 0..1  -> 64 rows each
    int warp_n = warp & 3;             // 0..3  -> 32 cols each
    int m0 = blockIdx.y * GBM;
    int n0 = blockIdx.x * GBN;

    int ar  = lane >> 2;               // 0..7
    int ac  = lane & 3;                // 0..3
    int ac2 = ac * 2;

    float c[4][4][4];                  // [mtile][ntile][reg]
#pragma unroll
    for (int i = 0; i < 4; i++)
#pragma unroll
        for (int j = 0; j < 4; j++)
#pragma unroll
            for (int r = 0; r < 4; r++) c[i][j][r] = 0.f;

    int nphase = (A2 != nullptr) ? 2 : 1;
    for (int ph = 0; ph < nphase; ph++) {
        const float* Ag = ph ? A2 : A1;
        const float* Bg = ph ? B2 : B1;
        bool doScale = (ph == 0) && (rdeg != nullptr);

        for (int k0 = 0; k0 < D; k0 += GBK) {
            // ---- stage A tile: 128 rows x 16 k (2 float4 per thread)
#pragma unroll
            for (int u = 0; u < 2; u++) {
                int idx = u * 256 + tid;       // 0..511
                int row = idx >> 2;
                int kq  = (idx & 3) * 4;
                float4 v = make_float4(0.f, 0.f, 0.f, 0.f);
                int gm = m0 + row;
                if (gm < M) {
                    v = *(const float4*)(Ag + (size_t)gm * D + k0 + kq);
                    if (doScale) {
                        float s = rdeg[gm];
                        v.x *= s; v.y *= s; v.z *= s; v.w *= s;
                    }
                }
                *(float4*)&As[row * AS_STRIDE + kq] = v;
            }
            // ---- stage B tile: 16 k x 128 n (2 float4 per thread)
#pragma unroll
            for (int u = 0; u < 2; u++) {
                int idx = u * 256 + tid;       // 0..511
                int row = idx >> 5;            // 0..15
                int nq  = (idx & 31) * 4;      // 0..124
                float4 v = *(const float4*)(Bg + (size_t)(k0 + row) * D + n0 + nq);
                *(float4*)&Bs[row * BS_STRIDE + nq] = v;
            }
            __syncthreads();

#pragma unroll
            for (int k8 = 0; k8 < GBK; k8 += 8) {
                unsigned af[4][4];
#pragma unroll
                for (int i = 0; i < 4; i++) {
                    int base = warp_m * 64 + i * 16;
                    af[i][0] = f2tf32(As[(base + ar)     * AS_STRIDE + k8 + ac]);
                    af[i][1] = f2tf32(As[(base + 8 + ar) * AS_STRIDE + k8 + ac]);
                    af[i][2] = f2tf32(As[(base + ar)     * AS_STRIDE + k8 + 4 + ac]);
                    af[i][3] = f2tf32(As[(base + 8 + ar) * AS_STRIDE + k8 + 4 + ac]);
                }
                unsigned bf[4][2];
#pragma unroll
                for (int j = 0; j < 4; j++) {
                    int nb = warp_n * 32 + j * 8 + ar;
                    bf[j][0] = f2tf32(Bs[(k8 + ac)     * BS_STRIDE + nb]);
                    bf[j][1] = f2tf32(Bs[(k8 + 4 + ac) * BS_STRIDE + nb]);
                }
#pragma unroll
                for (int i = 0; i < 4; i++)
#pragma unroll
                    for (int j = 0; j < 4; j++) {
                        asm volatile(
                            "mma.sync.aligned.m16n8k8.row.col.f32.tf32.tf32.f32 "
                            "{%0,%1,%2,%3}, {%4,%5,%6,%7}, {%8,%9}, {%0,%1,%2,%3};"
                            : "+f"(c[i][j][0]), "+f"(c[i][j][1]),
                              "+f"(c[i][j][2]), "+f"(c[i][j][3])
                            : "r"(af[i][0]), "r"(af[i][1]),
                              "r"(af[i][2]), "r"(af[i][3]),
                              "r"(bf[j][0]), "r"(bf[j][1]));
                    }
            }
            __syncthreads();
        }
    }

    // ---- epilogue: bias + relu + store (float2 per fragment half)
#pragma unroll
    for (int j = 0; j < 4; j++) {
        int gn = n0 + warp_n * 32 + j * 8 + ac2;
        float2 bv = make_float2(0.f, 0.f);
        if (bias != nullptr) bv = *(const float2*)(bias + gn);
#pragma unroll
        for (int i = 0; i < 4; i++) {
            int r0 = m0 + warp_m * 64 + i * 16 + ar;
            float2 v0 = make_float2(c[i][j][0] + bv.x, c[i][j][1] + bv.y);
            float2 v1 = make_float2(c[i][j][2] + bv.x, c[i][j][3] + bv.y);
            if (relu) {
                v0.x = fmaxf(v0.x, 0.f); v0.y = fmaxf(v0.y, 0.f);
                v1.x = fmaxf(v1.x, 0.f); v1.y = fmaxf(v1.y, 0.f);
            }
            if (r0 < M)     *(float2*)(C + (size_t)r0 * D + gn)       = v0;
            if (r0 + 8 < M) *(float2*)(C + (size_t)(r0 + 8) * D + gn) = v1;
        }
    }
}

// ---------------------------------------------------------------- edge MLP
__global__ void __launch_bounds__(256) edge_kernel(
    const int* __restrict__ ei,
    const float* __restrict__ Ab, const float* __restrict__ Bb,
    const float* __restrict__ bm1, const float* __restrict__ Wm2,
    const float* __restrict__ bm2, float* __restrict__ out, int E)
{
    int e = blockIdx.x * 8 + (threadIdx.x >> 5);
    if (e >= E) return;
    int lane = threadIdx.x & 31;
    int src = ei[e];
    int dst = ei[E + e];

    const float4* a  = (const float4*)(Ab + (size_t)src * D);
    const float4* b  = (const float4*)(Bb + (size_t)dst * D);
    const float4* bi = (const float4*)bm1;

    float acc0 = 0.f, acc1 = 0.f;
#pragma unroll
    for (int i = 0; i < 2; i++) {
        int q = lane + i * 32;
        float4 av = a[q];
        float4 bv = b[q];
        float4 cv = bi[q];
        float h0 = fmaxf(av.x + bv.x + cv.x, 0.f);
        float h1 = fmaxf(av.y + bv.y + cv.y, 0.f);
        float h2 = fmaxf(av.z + bv.z + cv.z, 0.f);
        float h3 = fmaxf(av.w + bv.w + cv.w, 0.f);
        const float4* w = (const float4*)(Wm2 + q * 8);
        float4 w0 = w[0];
        float4 w1 = w[1];
        acc0 = fmaf(h0, w0.x, acc0); acc1 = fmaf(h0, w0.y, acc1);
        acc0 = fmaf(h1, w0.z, acc0); acc1 = fmaf(h1, w0.w, acc1);
        acc0 = fmaf(h2, w1.x, acc0); acc1 = fmaf(h2, w1.y, acc1);
        acc0 = fmaf(h3, w1.z, acc0); acc1 = fmaf(h3, w1.w, acc1);
    }
#pragma unroll
    for (int off = 16; off > 0; off >>= 1) {
        acc0 += __shfl_xor_sync(0xFFFFFFFFu, acc0, off);
        acc1 += __shfl_xor_sync(0xFFFFFFFFu, acc1, off);
    }
    if (lane == 0) {
        out[(size_t)e * 2 + 0] = acc0 + bm2[0];
        out[(size_t)e * 2 + 1] = acc1 + bm2[1];
    }
}

// ---------------------------------------------------------------- launch
extern "C" void kernel_launch(void* const* d_in, const int* in_sizes, int n_in,
                              void* d_out, int out_size)
{
    const float* x   = (const float*)d_in[0];
    const int*   ei  = (const int*)d_in[1];        // int32 [2, E]
    const float* W1l = (const float*)d_in[2];
    const float* b1l = (const float*)d_in[3];
    const float* W1r = (const float*)d_in[4];
    const float* W2l = (const float*)d_in[5];
    const float* b2l = (const float*)d_in[6];
    const float* W2r = (const float*)d_in[7];
    const float* Wm1 = (const float*)d_in[8];      // [512, 256]
    const float* bm1 = (const float*)d_in[9];
    const float* Wm2 = (const float*)d_in[10];     // [256, 2]
    const float* bm2 = (const float*)d_in[11];
    float*       out = (float*)d_out;

    int M = in_sizes[0] / D;       // 50000
    int E = in_sizes[1] / 2;       // 800000

    float *msg, *deg, *rdeg, *h1, *h2, *Ab, *Bb;
    cudaGetSymbolAddress((void**)&msg,  g_msg);
    cudaGetSymbolAddress((void**)&deg,  g_deg);
    cudaGetSymbolAddress((void**)&rdeg, g_rdeg);
    cudaGetSymbolAddress((void**)&h1,   g_h1);
    cudaGetSymbolAddress((void**)&h2,   g_h2);
    cudaGetSymbolAddress((void**)&Ab,   g_Ab);
    cudaGetSymbolAddress((void**)&Bb,   g_Bb);

    int msg4 = M * D / 4;
    dim3 ggrid(D / GBN, (M + GBM - 1) / GBM);   // (2, 391)
    int eblocks = (E + 7) / 8;

    // ---- layer 1 ----
    zero_kernel<<<2048, 256>>>((float4*)msg, msg4);
    zero_kernel<<<64, 256>>>((float4*)deg, M / 4);
    scatter_kernel<<<eblocks, 256>>>(ei, x, msg, deg, E);
    rdeg_kernel<<<(M + 255) / 256, 256>>>(deg, rdeg, M);
    mma_gemm_kernel<<<ggrid, 256>>>(msg, W1l, x, W1r, rdeg, b1l, h1, M, 1);

    // ---- layer 2 ----
    zero_kernel<<<2048, 256>>>((float4*)msg, msg4);
    scatter_kernel<<<eblocks, 256>>>(ei, h1, msg, nullptr, E);
    mma_gemm_kernel<<<ggrid, 256>>>(msg, W2l, h1, W2r, rdeg, b2l, h2, M, 1);

    // ---- edge MLP node precompute ----
    mma_gemm_kernel<<<ggrid, 256>>>(h2, Wm1,           nullptr, nullptr,
                                    nullptr, nullptr, Ab, M, 0);
    mma_gemm_kernel<<<ggrid, 256>>>(h2, Wm1 + 256 * D, nullptr, nullptr,
                                    nullptr, nullptr, Bb, M, 0);

    // ---- per-edge ----
    edge_kernel<<<eblocks, 256>>>(ei, Ab, Bb, bm1, Wm2, bm2, out, E);
}

// round 10
// speedup vs baseline: 2.5486x; 1.9291x over previous
#include <cuda_runtime.h>
#include <cuda_bf16.h>

// ---------------------------------------------------------------------------
// EdgeClassifierGNN: 2x SAGEConv(mean) + edge MLP.
//   CSR built per call; aggregation = warp-per-node gather (no float atomics).
//   GEMMs: mma.sync m16n8k8 tf32, fp32 accumulate.
//   Edge MLP factored: out[e] = relu(A[src]+B[dst]+bm1) @ Wm2 + bm2
// ---------------------------------------------------------------------------

#define MAXN 50000
#define MAXE 800000
#define D 256

__device__ __align__(16) float g_msg [(size_t)MAXN * D];
__device__ __align__(16) float g_rdeg[MAXN];
__device__ __align__(16) float g_h1  [(size_t)MAXN * D];
__device__ __align__(16) float g_h2  [(size_t)MAXN * D];
__device__ __align__(16) float g_Ab  [(size_t)MAXN * D];
__device__ __align__(16) float g_Bb  [(size_t)MAXN * D];
__device__ int g_deg   [MAXN];
__device__ int g_rowptr[MAXN + 1];
__device__ int g_cursor[MAXN];
__device__ int g_elist [MAXE];

// ---------------------------------------------------------------- zero int
__global__ void zeroi_kernel(int* __restrict__ p, int n) {
    int i = blockIdx.x * blockDim.x + threadIdx.x;
    if (i < n) p[i] = 0;
}

// ---------------------------------------------------------------- histogram
__global__ void hist_kernel(const int* __restrict__ ei, int* __restrict__ deg,
                            int E)
{
    int e = blockIdx.x * blockDim.x + threadIdx.x;
    if (e < E) atomicAdd(deg + ei[E + e], 1);
}

// ---------------------------------------------------------------- scan
// single-block exclusive prefix over deg -> rowptr/cursor; also rdeg.
__global__ void scan_kernel(const int* __restrict__ deg,
                            int* __restrict__ rowptr, int* __restrict__ cursor,
                            float* __restrict__ rdeg, int n)
{
    __shared__ int sdata[1024];
    __shared__ int carry_s;
    if (threadIdx.x == 0) carry_s = 0;
    __syncthreads();

    for (int base = 0; base < n; base += 1024) {
        int i = base + threadIdx.x;
        int v = (i < n) ? deg[i] : 0;
        sdata[threadIdx.x] = v;
        __syncthreads();
#pragma unroll
        for (int off = 1; off < 1024; off <<= 1) {
            int t = (threadIdx.x >= off) ? sdata[threadIdx.x - off] : 0;
            __syncthreads();
            sdata[threadIdx.x] += t;
            __syncthreads();
        }
        int incl = sdata[threadIdx.x] + carry_s;
        if (i < n) {
            rowptr[i + 1] = incl;
            cursor[i]     = incl - v;
            rdeg[i]       = 1.0f / fmaxf((float)v, 1.0f);
        }
        __syncthreads();
        if (threadIdx.x == 1023) carry_s = incl;
        __syncthreads();
    }
    if (threadIdx.x == 0) rowptr[0] = 0;
}

// ---------------------------------------------------------------- fill
__global__ void fill_kernel(const int* __restrict__ ei, int* __restrict__ cursor,
                            int* __restrict__ elist, int E)
{
    int e = blockIdx.x * blockDim.x + threadIdx.x;
    if (e >= E) return;
    int p = atomicAdd(cursor + ei[E + e], 1);
    elist[p] = ei[e];              // store src
}

// ---------------------------------------------------------------- gather agg
// warp per node: out[node] = (1/max(deg,1)) * sum_{e in row} X[src_e]
__global__ void __launch_bounds__(256) gather_kernel(
    const int* __restrict__ rowptr, const int* __restrict__ elist,
    const float* __restrict__ rdeg, const float* __restrict__ X,
    float* __restrict__ out, int M)
{
    int node = blockIdx.x * 8 + (threadIdx.x >> 5);
    if (node >= M) return;
    int lane = threadIdx.x & 31;
    int beg = rowptr[node], end = rowptr[node + 1];

    float4 a0 = make_float4(0.f, 0.f, 0.f, 0.f);
    float4 a1 = make_float4(0.f, 0.f, 0.f, 0.f);

    int i = beg;
    for (; i + 1 < end; i += 2) {
        int s0 = elist[i], s1 = elist[i + 1];
        const float4* x0 = (const float4*)(X + (size_t)s0 * D);
        const float4* x1 = (const float4*)(X + (size_t)s1 * D);
        float4 u0 = x0[lane],      v0 = x1[lane];
        float4 u1 = x0[lane + 32], v1 = x1[lane + 32];
        a0.x += u0.x + v0.x; a0.y += u0.y + v0.y;
        a0.z += u0.z + v0.z; a0.w += u0.w + v0.w;
        a1.x += u1.x + v1.x; a1.y += u1.y + v1.y;
        a1.z += u1.z + v1.z; a1.w += u1.w + v1.w;
    }
    if (i < end) {
        int s0 = elist[i];
        const float4* x0 = (const float4*)(X + (size_t)s0 * D);
        float4 u0 = x0[lane], u1 = x0[lane + 32];
        a0.x += u0.x; a0.y += u0.y; a0.z += u0.z; a0.w += u0.w;
        a1.x += u1.x; a1.y += u1.y; a1.z += u1.z; a1.w += u1.w;
    }

    float r = rdeg[node];
    a0.x *= r; a0.y *= r; a0.z *= r; a0.w *= r;
    a1.x *= r; a1.y *= r; a1.z *= r; a1.w *= r;
    float4* o = (float4*)(out + (size_t)node * D);
    o[lane]      = a0;
    o[lane + 32] = a1;
}

// ---------------------------------------------------------------- tf32 GEMM
// C[M,256] = act( A1@B1 + A2@B2 + bias ), K = 256 per source.
#define GBM 128
#define GBN 128
#define GBK 16
#define AS_STRIDE 20
#define BS_STRIDE 136

__device__ __forceinline__ unsigned f2tf32(float f) {
    unsigned u;
    asm("cvt.rna.tf32.f32 %0, %1;" : "=r"(u) : "f"(f));
    return u;
}

__global__ void __launch_bounds__(256) mma_gemm_kernel(
    const float* __restrict__ A1, const float* __restrict__ B1,
    const float* __restrict__ A2, const float* __restrict__ B2,
    const float* __restrict__ bias,
    float* __restrict__ C, int M, int relu)
{
    __shared__ float As[GBM * AS_STRIDE];
    __shared__ float Bs[GBK * BS_STRIDE];

    int tid    = threadIdx.x;
    int warp   = tid >> 5;
    int lane   = tid & 31;
    int warp_m = warp >> 2;
    int warp_n = warp & 3;
    int m0 = blockIdx.y * GBM;
    int n0 = blockIdx.x * GBN;

    int ar  = lane >> 2;
    int ac  = lane & 3;
    int ac2 = ac * 2;

    float c[4][4][4];
#pragma unroll
    for (int i = 0; i < 4; i++)
#pragma unroll
        for (int j = 0; j < 4; j++)
#pragma unroll
            for (int r = 0; r < 4; r++) c[i][j][r] = 0.f;

    int nphase = (A2 != nullptr) ? 2 : 1;
    for (int ph = 0; ph < nphase; ph++) {
        const float* Ag = ph ? A2 : A1;
        const float* Bg = ph ? B2 : B1;

        for (int k0 = 0; k0 < D; k0 += GBK) {
#pragma unroll
            for (int u = 0; u < 2; u++) {
                int idx = u * 256 + tid;
                int row = idx >> 2;
                int kq  = (idx & 3) * 4;
                float4 v = make_float4(0.f, 0.f, 0.f, 0.f);
                int gm = m0 + row;
                if (gm < M)
                    v = *(const float4*)(Ag + (size_t)gm * D + k0 + kq);
                *(float4*)&As[row * AS_STRIDE + kq] = v;
            }
#pragma unroll
            for (int u = 0; u < 2; u++) {
                int idx = u * 256 + tid;
                int row = idx >> 5;
                int nq  = (idx & 31) * 4;
                float4 v = *(const float4*)(Bg + (size_t)(k0 + row) * D + n0 + nq);
                *(float4*)&Bs[row * BS_STRIDE + nq] = v;
            }
            __syncthreads();

#pragma unroll
            for (int k8 = 0; k8 < GBK; k8 += 8) {
                unsigned af[4][4];
#pragma unroll
                for (int i = 0; i < 4; i++) {
                    int base = warp_m * 64 + i * 16;
                    af[i][0] = f2tf32(As[(base + ar)     * AS_STRIDE + k8 + ac]);
                    af[i][1] = f2tf32(As[(base + 8 + ar) * AS_STRIDE + k8 + ac]);
                    af[i][2] = f2tf32(As[(base + ar)     * AS_STRIDE + k8 + 4 + ac]);
                    af[i][3] = f2tf32(As[(base + 8 + ar) * AS_STRIDE + k8 + 4 + ac]);
                }
                unsigned bf[4][2];
#pragma unroll
                for (int j = 0; j < 4; j++) {
                    int nb = warp_n * 32 + j * 8 + ar;
                    bf[j][0] = f2tf32(Bs[(k8 + ac)     * BS_STRIDE + nb]);
                    bf[j][1] = f2tf32(Bs[(k8 + 4 + ac) * BS_STRIDE + nb]);
                }
#pragma unroll
                for (int i = 0; i < 4; i++)
#pragma unroll
                    for (int j = 0; j < 4; j++) {
                        asm volatile(
                            "mma.sync.aligned.m16n8k8.row.col.f32.tf32.tf32.f32 "
                            "{%0,%1,%2,%3}, {%4,%5,%6,%7}, {%8,%9}, {%0,%1,%2,%3};"
                            : "+f"(c[i][j][0]), "+f"(c[i][j][1]),
                              "+f"(c[i][j][2]), "+f"(c[i][j][3])
                            : "r"(af[i][0]), "r"(af[i][1]),
                              "r"(af[i][2]), "r"(af[i][3]),
                              "r"(bf[j][0]), "r"(bf[j][1]));
                    }
            }
            __syncthreads();
        }
    }

#pragma unroll
    for (int j = 0; j < 4; j++) {
        int gn = n0 + warp_n * 32 + j * 8 + ac2;
        float2 bv = make_float2(0.f, 0.f);
        if (bias != nullptr) bv = *(const float2*)(bias + gn);
#pragma unroll
        for (int i = 0; i < 4; i++) {
            int r0 = m0 + warp_m * 64 + i * 16 + ar;
            float2 v0 = make_float2(c[i][j][0] + bv.x, c[i][j][1] + bv.y);
            float2 v1 = make_float2(c[i][j][2] + bv.x, c[i][j][3] + bv.y);
            if (relu) {
                v0.x = fmaxf(v0.x, 0.f); v0.y = fmaxf(v0.y, 0.f);
                v1.x = fmaxf(v1.x, 0.f); v1.y = fmaxf(v1.y, 0.f);
            }
            if (r0 < M)     *(float2*)(C + (size_t)r0 * D + gn)       = v0;
            if (r0 + 8 < M) *(float2*)(C + (size_t)(r0 + 8) * D + gn) = v1;
        }
    }
}

// ---------------------------------------------------------------- edge MLP
__global__ void __launch_bounds__(256) edge_kernel(
    const int* __restrict__ ei,
    const float* __restrict__ Ab, const float* __restrict__ Bb,
    const float* __restrict__ bm1, const float* __restrict__ Wm2,
    const float* __restrict__ bm2, float* __restrict__ out, int E)
{
    int e = blockIdx.x * 8 + (threadIdx.x >> 5);
    if (e >= E) return;
    int lane = threadIdx.x & 31;
    int src = ei[e];
    int dst = ei[E + e];

    const float4* a  = (const float4*)(Ab + (size_t)src * D);
    const float4* b  = (const float4*)(Bb + (size_t)dst * D);
    const float4* bi = (const float4*)bm1;

    float acc0 = 0.f, acc1 = 0.f;
#pragma unroll
    for (int i = 0; i < 2; i++) {
        int q = lane + i * 32;
        float4 av = a[q];
        float4 bv = b[q];
        float4 cv = bi[q];
        float h0 = fmaxf(av.x + bv.x + cv.x, 0.f);
        float h1 = fmaxf(av.y + bv.y + cv.y, 0.f);
        float h2 = fmaxf(av.z + bv.z + cv.z, 0.f);
        float h3 = fmaxf(av.w + bv.w + cv.w, 0.f);
        const float4* w = (const float4*)(Wm2 + q * 8);
        float4 w0 = w[0];
        float4 w1 = w[1];
        acc0 = fmaf(h0, w0.x, acc0); acc1 = fmaf(h0, w0.y, acc1);
        acc0 = fmaf(h1, w0.z, acc0); acc1 = fmaf(h1, w0.w, acc1);
        acc0 = fmaf(h2, w1.x, acc0); acc1 = fmaf(h2, w1.y, acc1);
        acc0 = fmaf(h3, w1.z, acc0); acc1 = fmaf(h3, w1.w, acc1);
    }
#pragma unroll
    for (int off = 16; off > 0; off >>= 1) {
        acc0 += __shfl_xor_sync(0xFFFFFFFFu, acc0, off);
        acc1 += __shfl_xor_sync(0xFFFFFFFFu, acc1, off);
    }
    if (lane == 0) {
        out[(size_t)e * 2 + 0] = acc0 + bm2[0];
        out[(size_t)e * 2 + 1] = acc1 + bm2[1];
    }
}

// ---------------------------------------------------------------- launch
extern "C" void kernel_launch(void* const* d_in, const int* in_sizes, int n_in,
                              void* d_out, int out_size)
{
    const float* x   = (const float*)d_in[0];
    const int*   ei  = (const int*)d_in[1];        // int32 [2, E]
    const float* W1l = (const float*)d_in[2];
    const float* b1l = (const float*)d_in[3];
    const float* W1r = (const float*)d_in[4];
    const float* W2l = (const float*)d_in[5];
    const float* b2l = (const float*)d_in[6];
    const float* W2r = (const float*)d_in[7];
    const float* Wm1 = (const float*)d_in[8];      // [512, 256]
    const float* bm1 = (const float*)d_in[9];
    const float* Wm2 = (const float*)d_in[10];     // [256, 2]
    const float* bm2 = (const float*)d_in[11];
    float*       out = (float*)d_out;

    int M = in_sizes[0] / D;       // 50000
    int E = in_sizes[1] / 2;       // 800000

    float *msg, *rdeg, *h1, *h2, *Ab, *Bb;
    int *deg, *rowptr, *cursor, *elist;
    cudaGetSymbolAddress((void**)&msg,    g_msg);
    cudaGetSymbolAddress((void**)&rdeg,   g_rdeg);
    cudaGetSymbolAddress((void**)&h1,     g_h1);
    cudaGetSymbolAddress((void**)&h2,     g_h2);
    cudaGetSymbolAddress((void**)&Ab,     g_Ab);
    cudaGetSymbolAddress((void**)&Bb,     g_Bb);
    cudaGetSymbolAddress((void**)&deg,    g_deg);
    cudaGetSymbolAddress((void**)&rowptr, g_rowptr);
    cudaGetSymbolAddress((void**)&cursor, g_cursor);
    cudaGetSymbolAddress((void**)&elist,  g_elist);

    dim3 ggrid(D / GBN, (M + GBM - 1) / GBM);   // (2, 391)
    int eb256 = (E + 255) / 256;
    int nblk  = (M + 7) / 8;

    // ---- CSR build (shared by both layers) ----
    zeroi_kernel<<<(M + 255) / 256, 256>>>(deg, M);
    hist_kernel<<<eb256, 256>>>(ei, deg, E);
    scan_kernel<<<1, 1024>>>(deg, rowptr, cursor, rdeg, M);
    fill_kernel<<<eb256, 256>>>(ei, cursor, elist, E);

    // ---- layer 1 ----
    gather_kernel<<<nblk, 256>>>(rowptr, elist, rdeg, x, msg, M);
    mma_gemm_kernel<<<ggrid, 256>>>(msg, W1l, x, W1r, b1l, h1, M, 1);

    // ---- layer 2 ----
    gather_kernel<<<nblk, 256>>>(rowptr, elist, rdeg, h1, msg, M);
    mma_gemm_kernel<<<ggrid, 256>>>(msg, W2l, h1, W2r, b2l, h2, M, 1);

    // ---- edge MLP node precompute ----
    mma_gemm_kernel<<<ggrid, 256>>>(h2, Wm1,           nullptr, nullptr,
                                    nullptr, Ab, M, 0);
    mma_gemm_kernel<<<ggrid, 256>>>(h2, Wm1 + 256 * D, nullptr, nullptr,
                                    nullptr, Bb, M, 0);

    // ---- per-edge ----
    edge_kernel<<<(E + 7) / 8, 256>>>(ei, Ab, Bb, bm1, Wm2, bm2, out, E);
}

// round 12
// speedup vs baseline: 3.3179x; 1.3019x over previous
#include <cuda_runtime.h>
#include <cuda_bf16.h>

// ---------------------------------------------------------------------------
// EdgeClassifierGNN: 2x SAGEConv(mean) + edge MLP.
//   CSR built per call; aggregation = warp-per-node gather (no float atomics).
//   GEMMs: mma.sync m16n8k8 tf32, fp32 accumulate, cp.async double-buffered.
//   Edge MLP factored: AB[:, :256]=h2@Wm1_top, AB[:,256:]=h2@Wm1_bot (one GEMM)
//   out[e] = relu(AB[src,:256]+AB[dst,256:]+bm1) @ Wm2 + bm2
// ---------------------------------------------------------------------------

#define MAXN 50000
#define MAXE 800000
#define D 256
#define LDAB 512

__device__ __align__(16) float g_msg [(size_t)MAXN * D];
__device__ __align__(16) float g_rdeg[MAXN];
__device__ __align__(16) float g_h1  [(size_t)MAXN * D];
__device__ __align__(16) float g_h2  [(size_t)MAXN * D];
__device__ __align__(16) float g_AB  [(size_t)MAXN * LDAB];
__device__ int g_deg   [MAXN];
__device__ int g_rowptr[MAXN + 1];
__device__ int g_cursor[MAXN];
__device__ int g_elist [MAXE];

// ---------------------------------------------------------------- zero int
__global__ void zeroi_kernel(int* __restrict__ p, int n) {
    int i = blockIdx.x * blockDim.x + threadIdx.x;
    if (i < n) p[i] = 0;
}

// ---------------------------------------------------------------- histogram
__global__ void hist_kernel(const int* __restrict__ ei, int* __restrict__ deg,
                            int E)
{
    int e = blockIdx.x * blockDim.x + threadIdx.x;
    if (e < E) atomicAdd(deg + ei[E + e], 1);
}

// ---------------------------------------------------------------- scan
__global__ void scan_kernel(const int* __restrict__ deg,
                            int* __restrict__ rowptr, int* __restrict__ cursor,
                            float* __restrict__ rdeg, int n)
{
    __shared__ int sdata[1024];
    __shared__ int carry_s;
    if (threadIdx.x == 0) carry_s = 0;
    __syncthreads();

    for (int base = 0; base < n; base += 1024) {
        int i = base + threadIdx.x;
        int v = (i < n) ? deg[i] : 0;
        sdata[threadIdx.x] = v;
        __syncthreads();
#pragma unroll
        for (int off = 1; off < 1024; off <<= 1) {
            int t = (threadIdx.x >= off) ? sdata[threadIdx.x - off] : 0;
            __syncthreads();
            sdata[threadIdx.x] += t;
            __syncthreads();
        }
        int incl = sdata[threadIdx.x] + carry_s;
        if (i < n) {
            rowptr[i + 1] = incl;
            cursor[i]     = incl - v;
            rdeg[i]       = 1.0f / fmaxf((float)v, 1.0f);
        }
        __syncthreads();
        if (threadIdx.x == 1023) carry_s = incl;
        __syncthreads();
    }
    if (threadIdx.x == 0) rowptr[0] = 0;
}

// ---------------------------------------------------------------- fill
__global__ void fill_kernel(const int* __restrict__ ei, int* __restrict__ cursor,
                            int* __restrict__ elist, int E)
{
    int e = blockIdx.x * blockDim.x + threadIdx.x;
    if (e >= E) return;
    int p = atomicAdd(cursor + ei[E + e], 1);
    elist[p] = ei[e];              // store src
}

// ---------------------------------------------------------------- gather agg
__global__ void __launch_bounds__(256) gather_kernel(
    const int* __restrict__ rowptr, const int* __restrict__ elist,
    const float* __restrict__ rdeg, const float* __restrict__ X,
    float* __restrict__ out, int M)
{
    int node = blockIdx.x * 8 + (threadIdx.x >> 5);
    if (node >= M) return;
    int lane = threadIdx.x & 31;
    int beg = rowptr[node], end = rowptr[node + 1];

    float4 a0 = make_float4(0.f, 0.f, 0.f, 0.f);
    float4 a1 = make_float4(0.f, 0.f, 0.f, 0.f);

    int i = beg;
    for (; i + 1 < end; i += 2) {
        int s0 = elist[i], s1 = elist[i + 1];
        const float4* x0 = (const float4*)(X + (size_t)s0 * D);
        const float4* x1 = (const float4*)(X + (size_t)s1 * D);
        float4 u0 = x0[lane],      v0 = x1[lane];
        float4 u1 = x0[lane + 32], v1 = x1[lane + 32];
        a0.x += u0.x + v0.x; a0.y += u0.y + v0.y;
        a0.z += u0.z + v0.z; a0.w += u0.w + v0.w;
        a1.x += u1.x + v1.x; a1.y += u1.y + v1.y;
        a1.z += u1.z + v1.z; a1.w += u1.w + v1.w;
    }
    if (i < end) {
        int s0 = elist[i];
        const float4* x0 = (const float4*)(X + (size_t)s0 * D);
        float4 u0 = x0[lane], u1 = x0[lane + 32];
        a0.x += u0.x; a0.y += u0.y; a0.z += u0.z; a0.w += u0.w;
        a1.x += u1.x; a1.y += u1.y; a1.z += u1.z; a1.w += u1.w;
    }

    float r = rdeg[node];
    a0.x *= r; a0.y *= r; a0.z *= r; a0.w *= r;
    a1.x *= r; a1.y *= r; a1.z *= r; a1.w *= r;
    float4* o = (float4*)(out + (size_t)node * D);
    o[lane]      = a0;
    o[lane + 32] = a1;
}

// ---------------------------------------------------------------- tf32 GEMM
// C[M, ncols] = act( A1@B1 + A2@B2 + bias ), K = 256 per source phase.
// When B1hi != nullptr (single-phase only): blocks with n0 >= 256 use B1hi
// with column offset n0-256 (merged [Wm1_top | Wm1_bot] output).
#define GBM 128
#define GBN 128
#define GBK 16
#define AS_STRIDE 20
#define BS_STRIDE 136
#define KSTEPS (D / GBK)   // 16

__device__ __forceinline__ unsigned f2tf32(float f) {
    unsigned u;
    asm("cvt.rna.tf32.f32 %0, %1;" : "=r"(u) : "f"(f));
    return u;
}

__device__ __forceinline__ void cpa16(unsigned dst, const void* src, int nbytes) {
    asm volatile("cp.async.cg.shared.global [%0], [%1], 16, %2;\n"
                 :: "r"(dst), "l"(src), "r"(nbytes));
}

__global__ void __launch_bounds__(256) mma_gemm_kernel(
    const float* __restrict__ A1, const float* __restrict__ B1,
    const float* __restrict__ A2, const float* __restrict__ B2,
    const float* __restrict__ B1hi, const float* __restrict__ bias,
    float* __restrict__ C, int M, int ldc, int relu)
{
    __shared__ float As[2][GBM * AS_STRIDE];
    __shared__ float Bs[2][GBK * BS_STRIDE];

    int tid    = threadIdx.x;
    int warp   = tid >> 5;
    int lane   = tid & 31;
    int warp_m = warp >> 2;
    int warp_n = warp & 3;
    int m0 = blockIdx.y * GBM;
    int n0 = blockIdx.x * GBN;

    const float* Bg0 = B1;
    int nb0 = n0;
    if (B1hi != nullptr && n0 >= 256) { Bg0 = B1hi; nb0 = n0 - 256; }

    int ar  = lane >> 2;
    int ac  = lane & 3;
    int ac2 = ac * 2;

    float c[4][4][4];
#pragma unroll
    for (int i = 0; i < 4; i++)
#pragma unroll
        for (int j = 0; j < 4; j++)
#pragma unroll
            for (int r = 0; r < 4; r++) c[i][j][r] = 0.f;

    int nphase = (A2 != nullptr) ? 2 : 1;
    int niter  = nphase * KSTEPS;

    unsigned asb[2], bsb[2];
    asb[0] = (unsigned)__cvta_generic_to_shared(&As[0][0]);
    asb[1] = (unsigned)__cvta_generic_to_shared(&As[1][0]);
    bsb[0] = (unsigned)__cvta_generic_to_shared(&Bs[0][0]);
    bsb[1] = (unsigned)__cvta_generic_to_shared(&Bs[1][0]);

    auto issue = [&](int t, int buf) {
        int ph = t >> 4;                       // KSTEPS == 16
        int k0 = (t & (KSTEPS - 1)) * GBK;
        const float* Ag = ph ? A2 : A1;
        const float* Bg = ph ? B2 : Bg0;
        int nb = ph ? n0 : nb0;
#pragma unroll
        for (int u = 0; u < 2; u++) {
            int idx = u * 256 + tid;
            int row = idx >> 2;
            int kq  = (idx & 3) * 4;
            int gm  = m0 + row;
            bool ok = (gm < M);
            const float* src = Ag + (size_t)(ok ? gm : 0) * D + k0 + kq;
            cpa16(asb[buf] + (unsigned)(row * AS_STRIDE + kq) * 4, src, ok ? 16 : 0);
        }
#pragma unroll
        for (int u = 0; u < 2; u++) {
            int idx = u * 256 + tid;
            int row = idx >> 5;
            int nq  = (idx & 31) * 4;
            cpa16(bsb[buf] + (unsigned)(row * BS_STRIDE + nq) * 4,
                  Bg + (size_t)(k0 + row) * D + nb + nq, 16);
        }
        asm volatile("cp.async.commit_group;\n" ::: "memory");
    };

    issue(0, 0);

    for (int t = 0; t < niter; t++) {
        int buf = t & 1;
        if (t + 1 < niter) {
            issue(t + 1, buf ^ 1);
            asm volatile("cp.async.wait_group 1;\n" ::: "memory");
        } else {
            asm volatile("cp.async.wait_group 0;\n" ::: "memory");
        }
        __syncthreads();

        const float* Asb = As[buf];
        const float* Bsb = Bs[buf];
#pragma unroll
        for (int k8 = 0; k8 < GBK; k8 += 8) {
            unsigned af[4][4];
#pragma unroll
            for (int i = 0; i < 4; i++) {
                int base = warp_m * 64 + i * 16;
                af[i][0] = f2tf32(Asb[(base + ar)     * AS_STRIDE + k8 + ac]);
                af[i][1] = f2tf32(Asb[(base + 8 + ar) * AS_STRIDE + k8 + ac]);
                af[i][2] = f2tf32(Asb[(base + ar)     * AS_STRIDE + k8 + 4 + ac]);
                af[i][3] = f2tf32(Asb[(base + 8 + ar) * AS_STRIDE + k8 + 4 + ac]);
            }
            unsigned bf[4][2];
#pragma unroll
            for (int j = 0; j < 4; j++) {
                int nb = warp_n * 32 + j * 8 + ar;
                bf[j][0] = f2tf32(Bsb[(k8 + ac)     * BS_STRIDE + nb]);
                bf[j][1] = f2tf32(Bsb[(k8 + 4 + ac) * BS_STRIDE + nb]);
            }
#pragma unroll
            for (int i = 0; i < 4; i++)
#pragma unroll
                for (int j = 0; j < 4; j++) {
                    asm volatile(
                        "mma.sync.aligned.m16n8k8.row.col.f32.tf32.tf32.f32 "
                        "{%0,%1,%2,%3}, {%4,%5,%6,%7}, {%8,%9}, {%0,%1,%2,%3};"
                        : "+f"(c[i][j][0]), "+f"(c[i][j][1]),
                          "+f"(c[i][j][2]), "+f"(c[i][j][3])
                        : "r"(af[i][0]), "r"(af[i][1]),
                          "r"(af[i][2]), "r"(af[i][3]),
                          "r"(bf[j][0]), "r"(bf[j][1]));
                }
        }
        __syncthreads();
    }

#pragma unroll
    for (int j = 0; j < 4; j++) {
        int gn = n0 + warp_n * 32 + j * 8 + ac2;
        float2 bv = make_float2(0.f, 0.f);
        if (bias != nullptr) bv = *(const float2*)(bias + gn);
#pragma unroll
        for (int i = 0; i < 4; i++) {
            int r0 = m0 + warp_m * 64 + i * 16 + ar;
            float2 v0 = make_float2(c[i][j][0] + bv.x, c[i][j][1] + bv.y);
            float2 v1 = make_float2(c[i][j][2] + bv.x, c[i][j][3] + bv.y);
            if (relu) {
                v0.x = fmaxf(v0.x, 0.f); v0.y = fmaxf(v0.y, 0.f);
                v1.x = fmaxf(v1.x, 0.f); v1.y = fmaxf(v1.y, 0.f);
            }
            if (r0 < M)     *(float2*)(C + (size_t)r0 * ldc + gn)       = v0;
            if (r0 + 8 < M) *(float2*)(C + (size_t)(r0 + 8) * ldc + gn) = v1;
        }
    }
}

// ---------------------------------------------------------------- edge MLP
// warp per edge (grid-stride); bias/Wm2 hoisted into registers.
__global__ void __launch_bounds__(256) edge_kernel(
    const int* __restrict__ ei, const float* __restrict__ AB,
    const float* __restrict__ bm1, const float* __restrict__ Wm2,
    const float* __restrict__ bm2, float* __restrict__ out,
    int E, int warpsTotal)
{
    int warpId = blockIdx.x * 8 + (threadIdx.x >> 5);
    int lane   = threadIdx.x & 31;
    int q0 = lane, q1 = lane + 32;

    const float4* bi = (const float4*)bm1;
    float4 cv0 = bi[q0], cv1 = bi[q1];
    const float4* w = (const float4*)Wm2;
    float4 w00 = w[q0 * 2], w01 = w[q0 * 2 + 1];
    float4 w10 = w[q1 * 2], w11 = w[q1 * 2 + 1];
    float bb0 = bm2[0], bb1 = bm2[1];

    for (int e = warpId; e < E; e += warpsTotal) {
        int src = ei[e];
        int dst = ei[E + e];
        const float4* a = (const float4*)(AB + (size_t)src * LDAB);
        const float4* b = (const float4*)(AB + (size_t)dst * LDAB + 256);

        float4 a0 = a[q0], a1 = a[q1];
        float4 b0 = b[q0], b1 = b[q1];

        float acc0, acc1;
        {
            float h0 = fmaxf(a0.x + b0.x + cv0.x, 0.f);
            float h1 = fmaxf(a0.y + b0.y + cv0.y, 0.f);
            float h2 = fmaxf(a0.z + b0.z + cv0.z, 0.f);
            float h3 = fmaxf(a0.w + b0.w + cv0.w, 0.f);
            acc0 = h0 * w00.x;              acc1 = h0 * w00.y;
            acc0 = fmaf(h1, w00.z, acc0);   acc1 = fmaf(h1, w00.w, acc1);
            acc0 = fmaf(h2, w01.x, acc0);   acc1 = fmaf(h2, w01.y, acc1);
            acc0 = fmaf(h3, w01.z, acc0);   acc1 = fmaf(h3, w01.w, acc1);
        }
        {
            float h0 = fmaxf(a1.x + b1.x + cv1.x, 0.f);
            float h1 = fmaxf(a1.y + b1.y + cv1.y, 0.f);
            float h2 = fmaxf(a1.z + b1.z + cv1.z, 0.f);
            float h3 = fmaxf(a1.w + b1.w + cv1.w, 0.f);
            acc0 = fmaf(h0, w10.x, acc0);   acc1 = fmaf(h0, w10.y, acc1);
            acc0 = fmaf(h1, w10.z, acc0);   acc1 = fmaf(h1, w10.w, acc1);
            acc0 = fmaf(h2, w11.x, acc0);   acc1 = fmaf(h2, w11.y, acc1);
            acc0 = fmaf(h3, w11.z, acc0);   acc1 = fmaf(h3, w11.w, acc1);
        }
#pragma unroll
        for (int off = 16; off > 0; off >>= 1) {
            acc0 += __shfl_xor_sync(0xFFFFFFFFu, acc0, off);
            acc1 += __shfl_xor_sync(0xFFFFFFFFu, acc1, off);
        }
        if (lane == 0) {
            float2 o = make_float2(acc0 + bb0, acc1 + bb1);
            *(float2*)(out + (size_t)e * 2) = o;
        }
    }
}

// ---------------------------------------------------------------- launch
extern "C" void kernel_launch(void* const* d_in, const int* in_sizes, int n_in,
                              void* d_out, int out_size)
{
    const float* x   = (const float*)d_in[0];
    const int*   ei  = (const int*)d_in[1];        // int32 [2, E]
    const float* W1l = (const float*)d_in[2];
    const float* b1l = (const float*)d_in[3];
    const float* W1r = (const float*)d_in[4];
    const float* W2l = (const float*)d_in[5];
    const float* b2l = (const float*)d_in[6];
    const float* W2r = (const float*)d_in[7];
    const float* Wm1 = (const float*)d_in[8];      // [512, 256]
    const float* bm1 = (const float*)d_in[9];
    const float* Wm2 = (const float*)d_in[10];     // [256, 2]
    const float* bm2 = (const float*)d_in[11];
    float*       out = (float*)d_out;

    int M = in_sizes[0] / D;       // 50000
    int E = in_sizes[1] / 2;       // 800000

    float *msg, *rdeg, *h1, *h2, *AB;
    int *deg, *rowptr, *cursor, *elist;
    cudaGetSymbolAddress((void**)&msg,    g_msg);
    cudaGetSymbolAddress((void**)&rdeg,   g_rdeg);
    cudaGetSymbolAddress((void**)&h1,     g_h1);
    cudaGetSymbolAddress((void**)&h2,     g_h2);
    cudaGetSymbolAddress((void**)&AB,     g_AB);
    cudaGetSymbolAddress((void**)&deg,    g_deg);
    cudaGetSymbolAddress((void**)&rowptr, g_rowptr);
    cudaGetSymbolAddress((void**)&cursor, g_cursor);
    cudaGetSymbolAddress((void**)&elist,  g_elist);

    dim3 ggrid(D / GBN, (M + GBM - 1) / GBM);      // (2, 391)
    dim3 mgrid(LDAB / GBN, (M + GBM - 1) / GBM);   // (4, 391)
    int eb256 = (E + 255) / 256;
    int nblk  = (M + 7) / 8;

    // ---- CSR build (shared by both layers) ----
    zeroi_kernel<<<(M + 255) / 256, 256>>>(deg, M);
    hist_kernel<<<eb256, 256>>>(ei, deg, E);
    scan_kernel<<<1, 1024>>>(deg, rowptr, cursor, rdeg, M);
    fill_kernel<<<eb256, 256>>>(ei, cursor, elist, E);

    // ---- layer 1 ----
    gather_kernel<<<nblk, 256>>>(rowptr, elist, rdeg, x, msg, M);
    mma_gemm_kernel<<<ggrid, 256>>>(msg, W1l, x, W1r, nullptr, b1l,
                                    h1, M, D, 1);

    // ---- layer 2 ----
    gather_kernel<<<nblk, 256>>>(rowptr, elist, rdeg, h1, msg, M);
    mma_gemm_kernel<<<ggrid, 256>>>(msg, W2l, h1, W2r, nullptr, b2l,
                                    h2, M, D, 1);

    // ---- edge MLP node precompute (merged A|B, one GEMM) ----
    mma_gemm_kernel<<<mgrid, 256>>>(h2, Wm1, nullptr, nullptr,
                                    Wm1 + 256 * D, nullptr, AB, M, LDAB, 0);

    // ---- per-edge ----
    int egrid = 6250;                              // 50000 warps, ~16 edges each
    edge_kernel<<<egrid, 256>>>(ei, AB, bm1, Wm2, bm2, out, E, egrid * 8);
}